// round 7
// baseline (speedup 1.0000x reference)
#include <cuda_runtime.h>
#include <cuda_bf16.h>
#include <cstdint>
#include <cstddef>

#define DEVFN __device__ __forceinline__

constexpr int TOK = 3072, DDIM = 2048, FDIM = 8192;
constexpr int WELEM = FDIM * DDIM;
constexpr int BM = 128, BN = 128, BK = 64;
constexpr int KITERS = DDIM / BK;            // 32
constexpr int TILE_B = BM * BK;              // 8192 B
constexpr int STAGE_B = 3 * TILE_B;          // 24576
constexpr int STAGES = 4;
constexpr int SMEM_GEMM = STAGES * STAGE_B;  // 98304

__device__ float d_part[3 * 512];
__device__ float d_wsinv[3];
__device__ uint8_t d_qa[(size_t)TOK * DDIM];
__device__ float d_ainv[TOK];
__device__ uint8_t d_qg[(size_t)FDIM * DDIM];
__device__ uint8_t d_qu[(size_t)FDIM * DDIM];
__device__ float d_v[FDIM];
__device__ float d_h[(size_t)TOK * FDIM];
__device__ float d_tok[TOK];
__device__ float d_pool[24];

DEVFN float wsum(float v) {
    #pragma unroll
    for (int o = 16; o; o >>= 1) v += __shfl_xor_sync(~0u, v, o);
    return v;
}
DEVFN float wmax(float v) {
    #pragma unroll
    for (int o = 16; o; o >>= 1) v = fmaxf(v, __shfl_xor_sync(~0u, v, o));
    return v;
}
DEVFN int8_t tern(float w, float ws) {
    return (int8_t)(int)fminf(fmaxf(rintf(w * ws), -1.f), 1.f);
}

// ---------------- K0: |W| partial sums ----------------
__global__ void wred_kernel(const float* __restrict__ Wg, const float* __restrict__ Wu,
                            const float* __restrict__ Wd) {
    int y = blockIdx.y;
    const float4* W = (const float4*)(y == 0 ? Wg : (y == 1 ? Wu : Wd));
    float s = 0.f;
    for (int i = blockIdx.x * 256 + threadIdx.x; i < WELEM / 4; i += 512 * 256) {
        float4 w = W[i];
        s += fabsf(w.x) + fabsf(w.y) + fabsf(w.z) + fabsf(w.w);
    }
    s = wsum(s);
    __shared__ float rs[8];
    if ((threadIdx.x & 31) == 0) rs[threadIdx.x >> 5] = s;
    __syncthreads();
    if (threadIdx.x == 0) {
        float S = 0.f;
        #pragma unroll
        for (int k = 0; k < 8; k++) S += rs[k];
        d_part[y * 512 + blockIdx.x] = S;
    }
}

// packed fragment addressing
DEVFN size_t a_addr(int m, int g) {
    int kb = g >> 4;
    int i4 = (m & 127) >> 4;
    int s = (g >> 3) & 1;
    int t = ((m & 7) << 2) | (g & 3);
    int r = ((m >> 3) & 1) | (((g >> 2) & 1) << 1);
    return ((size_t)((m >> 7) * 32 + kb) << 13) + (((s * 8 + i4) * 32 + t) << 4) + r * 4;
}
DEVFN size_t b_addr(int n, int g) {
    int kb = g >> 4;
    int j = (n & 127) >> 3;
    int s = (g >> 3) & 1;
    int t = ((n & 7) << 2) | (g & 3);
    int r = (g >> 2) & 1;
    return ((size_t)((n >> 7) * 32 + kb) << 13) + (((s * 16 + j) * 32 + t) << 3) + r * 4;
}

// ---------------- K1: ternary quant Wg,Wu (inline scale); zero d_v ----------------
__global__ void qw2_kernel(const float* __restrict__ Wg, const float* __restrict__ Wu) {
    int y = blockIdx.y, tid = threadIdx.x;
    float ps = 0.f;
    #pragma unroll
    for (int k = 0; k < 2; k++) ps += d_part[y * 512 + tid * 2 + k];
    ps = wsum(ps);
    __shared__ float rs[8];
    __shared__ float sws;
    if ((tid & 31) == 0) rs[tid >> 5] = ps;
    __syncthreads();
    if (tid == 0) {
        float S = 0.f;
        #pragma unroll
        for (int k = 0; k < 8; k++) S += rs[k];
        float wm = fmaxf(S / (float)WELEM, 1e-5f);
        sws = wm;
        if (blockIdx.x == 0) d_wsinv[y] = wm;
    }
    __syncthreads();
    if (y == 0 && blockIdx.x < 32) d_v[blockIdx.x * 256 + tid] = 0.f;
    const float4* src = (const float4*)(y ? Wu : Wg);
    uint8_t* dst = y ? d_qu : d_qg;
    float ws = 1.0f / sws;
    int stride = gridDim.x * 256;
    for (int i = blockIdx.x * 256 + tid; i < WELEM / 4; i += stride) {
        int n = i >> 9, g = i & 511;
        float4 w = src[i];
        uint32_t p = (uint32_t)(uint8_t)tern(w.x, ws) |
                     ((uint32_t)(uint8_t)tern(w.y, ws) << 8) |
                     ((uint32_t)(uint8_t)tern(w.z, ws) << 16) |
                     ((uint32_t)(uint8_t)tern(w.w, ws) << 24);
        *(uint32_t*)(dst + b_addr(n, g)) = p;
    }
}

// ---------------- K2: activation quant -> packed int8 ----------------
__global__ void act_kernel(const float* __restrict__ x) {
    int m = blockIdx.x, tid = threadIdx.x;
    const float4* row = (const float4*)(x + (size_t)m * DDIM);
    float mx = 0.f;
    for (int i = tid; i < 512; i += 256) {
        float4 w = row[i];
        mx = fmaxf(mx, fmaxf(fmaxf(fabsf(w.x), fabsf(w.y)), fmaxf(fabsf(w.z), fabsf(w.w))));
    }
    mx = wmax(mx);
    __shared__ float rm[8], smv;
    if ((tid & 31) == 0) rm[tid >> 5] = mx;
    __syncthreads();
    if (tid == 0) {
        float M = 0.f;
        #pragma unroll
        for (int k = 0; k < 8; k++) M = fmaxf(M, rm[k]);
        smv = fmaxf(M, 1e-5f);
    }
    __syncthreads();
    float scale = 127.0f / smv;
    for (int g = tid; g < 512; g += 256) {
        float4 w = row[g];
        int q0 = (int)fminf(fmaxf(rintf(w.x * scale), -128.f), 127.f);
        int q1 = (int)fminf(fmaxf(rintf(w.y * scale), -128.f), 127.f);
        int q2 = (int)fminf(fmaxf(rintf(w.z * scale), -128.f), 127.f);
        int q3 = (int)fminf(fmaxf(rintf(w.w * scale), -128.f), 127.f);
        uint32_t p = (uint32_t)(uint8_t)q0 | ((uint32_t)(uint8_t)q1 << 8) |
                     ((uint32_t)(uint8_t)q2 << 16) | ((uint32_t)(uint8_t)q3 << 24);
        *(uint32_t*)(d_qa + a_addr(m, g)) = p;
    }
    if (tid == 0) d_ainv[m] = smv / 127.0f;
}

// ---------------- K3: hybrid tensor(32 cols)+dp4a(96 cols) double-GEMM ----------------
DEVFN void mma_s8(int* c, const uint32_t* a, uint32_t b0, uint32_t b1) {
    asm volatile(
        "mma.sync.aligned.m16n8k32.row.col.s32.s8.s8.s32 "
        "{%0,%1,%2,%3}, {%4,%5,%6,%7}, {%8,%9}, {%0,%1,%2,%3};"
        : "+r"(c[0]), "+r"(c[1]), "+r"(c[2]), "+r"(c[3])
        : "r"(a[0]), "r"(a[1]), "r"(a[2]), "r"(a[3]), "r"(b0), "r"(b1));
}

DEVFN void stage_copy(uint8_t* smem, int st, const uint8_t* gA, const uint8_t* gG,
                      const uint8_t* gU, int kb, int tid) {
    uint8_t* base = smem + st * STAGE_B;
    size_t koff = (size_t)kb * TILE_B + (size_t)(tid << 4);
    uint32_t d0;
    asm("{ .reg .u64 t; cvta.to.shared.u64 t, %1; cvt.u32.u64 %0, t; }"
        : "=r"(d0) : "l"(base + (tid << 4)));
    asm volatile("cp.async.cg.shared.global [%0], [%1], 16;" :: "r"(d0), "l"(gA + koff));
    asm volatile("cp.async.cg.shared.global [%0], [%1], 16;" :: "r"(d0 + TILE_B), "l"(gG + koff));
    asm volatile("cp.async.cg.shared.global [%0], [%1], 16;" :: "r"(d0 + 2 * TILE_B), "l"(gU + koff));
}

__global__ void __launch_bounds__(512, 1) gemm_kernel() {
    extern __shared__ uint8_t smem[];
    int tid = threadIdx.x, lane = tid & 31, wid = tid >> 5;
    int mb = blockIdx.y, nb = blockIdx.x;

    const uint8_t* gA = d_qa + ((size_t)mb << 18);
    const uint8_t* gG = d_qg + ((size_t)nb << 18);
    const uint8_t* gU = d_qu + ((size_t)nb << 18);

    int acc[64];
    #pragma unroll
    for (int k = 0; k < 64; k++) acc[k] = 0;

    // tensor warps: wid 0..3 (one per SMSP), n in [0,32)
    int wm2 = wid & 1;            // m half: 4 m16-tiles each
    int wn2 = (wid >> 1) & 1;     // n half: 2 j8-groups each
    // dp4a warps: wid 4..15 (3 per SMSP), n in [32,128)
    int dw = wid - 4;
    int mat = dw >= 6;            // 0 = G, 1 = U
    int w6 = mat ? dw - 6 : dw;   // 0..5
    int mrow = lane >> 1;         // 0..15: 8-row group
    int ncg = lane & 1;           // which of 2 col-groups
    int jg = 4 + w6 * 2 + ncg;    // B col-group 4..15
    int i4 = mrow >> 1, r0 = (mrow & 1) * 4;

    #pragma unroll
    for (int st = 0; st < 3; st++) {
        stage_copy(smem, st, gA, gG, gU, st, tid);
        asm volatile("cp.async.commit_group;" ::: "memory");
    }

    for (int kb = 0; kb < KITERS; kb++) {
        if (kb < 30)       asm volatile("cp.async.wait_group 2;" ::: "memory");
        else if (kb == 30) asm volatile("cp.async.wait_group 1;" ::: "memory");
        else               asm volatile("cp.async.wait_group 0;" ::: "memory");
        __syncthreads();

        if (kb + 3 < KITERS) {
            stage_copy(smem, (kb + 3) & 3, gA, gG, gU, kb + 3, tid);
            asm volatile("cp.async.commit_group;" ::: "memory");
        }

        const uint8_t* sA = smem + (kb & 3) * STAGE_B;
        const uint8_t* sG = sA + TILE_B;
        const uint8_t* sU = sA + 2 * TILE_B;

        if (wid < 4) {
            // -------- tensor path: n in [0,32) --------
            #pragma unroll
            for (int s = 0; s < 2; s++) {
                uint32_t af[4][4];
                #pragma unroll
                for (int mt = 0; mt < 4; mt++) {
                    uint4 v = *(const uint4*)(sA + (((s * 8 + wm2 * 4 + mt) * 32 + lane) << 4));
                    af[mt][0] = v.x; af[mt][1] = v.y; af[mt][2] = v.z; af[mt][3] = v.w;
                }
                #pragma unroll
                for (int j8 = 0; j8 < 2; j8++) {
                    int j = wn2 * 2 + j8;
                    uint2 bg = *(const uint2*)(sG + (((s * 16 + j) * 32 + lane) << 3));
                    uint2 bu = *(const uint2*)(sU + (((s * 16 + j) * 32 + lane) << 3));
                    #pragma unroll
                    for (int mt = 0; mt < 4; mt++) {
                        mma_s8(&acc[((mt * 2 + j8) * 2 + 0) * 4], af[mt], bg.x, bg.y);
                        mma_s8(&acc[((mt * 2 + j8) * 2 + 1) * 4], af[mt], bu.x, bu.y);
                    }
                }
            }
        } else {
            // -------- dp4a path: n in [32,128) --------
            const uint8_t* sB = mat ? sU : sG;
            #pragma unroll
            for (int s = 0; s < 2; s++) {
                #pragma unroll
                for (int g2 = 0; g2 < 4; g2++) {
                    int a0 = (((s * 8 + i4) * 32 + g2) << 4) + r0;
                    int av0[8], av1[8], bv0[8], bv1[8];
                    #pragma unroll
                    for (int i = 0; i < 8; i++) {
                        const uint8_t* p = sA + a0 + (i << 6);
                        av0[i] = *(const int*)p;
                        av1[i] = *(const int*)(p + 8);
                    }
                    #pragma unroll
                    for (int nc = 0; nc < 8; nc++) {
                        int2 b2 = *(const int2*)(sB + (((s * 16 + jg) * 32 + nc * 4 + g2) << 3));
                        bv0[nc] = b2.x; bv1[nc] = b2.y;
                    }
                    #pragma unroll
                    for (int i = 0; i < 8; i++)
                        #pragma unroll
                        for (int nc = 0; nc < 8; nc++)
                            acc[i * 8 + nc] = __dp4a(av1[i], bv1[nc],
                                              __dp4a(av0[i], bv0[nc], acc[i * 8 + nc]));
                }
            }
        }
    }

    __syncthreads();
    // dp4a G-warps publish int sums (128 rows x 96 cols)
    int* sx = (int*)smem;
    if (wid >= 4 && mat == 0) {
        #pragma unroll
        for (int i = 0; i < 8; i++)
            #pragma unroll
            for (int nc = 0; nc < 8; nc++)
                sx[(mrow * 8 + i) * 96 + w6 * 16 + ncg * 8 + nc] = acc[i * 8 + nc];
    }
    __syncthreads();

    float wsg = d_wsinv[0], wsu = d_wsinv[1];
    if (wid < 4) {
        // tensor epilogue: n in [0,32)
        #pragma unroll
        for (int mt = 0; mt < 4; mt++) {
            #pragma unroll
            for (int h2 = 0; h2 < 2; h2++) {
                int row = mb * 128 + (wm2 * 4 + mt) * 16 + h2 * 8 + (lane >> 2);
                float ai = d_ainv[row];
                float sg = wsg * ai, su = wsu * ai;
                float* drow = d_h + (size_t)row * FDIM;
                #pragma unroll
                for (int j8 = 0; j8 < 2; j8++) {
                    int n0 = nb * 128 + (wn2 * 2 + j8) * 8 + 2 * (lane & 3);
                    float g0 = (float)acc[((mt * 2 + j8) * 2 + 0) * 4 + h2 * 2] * sg;
                    float g1 = (float)acc[((mt * 2 + j8) * 2 + 0) * 4 + h2 * 2 + 1] * sg;
                    float u0 = (float)acc[((mt * 2 + j8) * 2 + 1) * 4 + h2 * 2] * su;
                    float u1 = (float)acc[((mt * 2 + j8) * 2 + 1) * 4 + h2 * 2 + 1] * su;
                    float2 o;
                    o.x = g0 / (1.f + __expf(-g0)) * u0;
                    o.y = g1 / (1.f + __expf(-g1)) * u1;
                    *(float2*)(drow + n0) = o;
                }
            }
        }
    } else if (mat == 1) {
        // dp4a combine epilogue: n in [32,128)
        #pragma unroll
        for (int i = 0; i < 8; i++) {
            int row = mb * 128 + mrow * 8 + i;
            float ai = d_ainv[row];
            float sg = wsg * ai, su = wsu * ai;
            float* drow = d_h + (size_t)row * FDIM + nb * 128 + 32 + w6 * 16 + ncg * 8;
            #pragma unroll
            for (int nc = 0; nc < 8; nc++) {
                float g = (float)sx[(mrow * 8 + i) * 96 + w6 * 16 + ncg * 8 + nc] * sg;
                float u = (float)acc[i * 8 + nc] * su;
                drow[nc] = g / (1.f + __expf(-g)) * u;
            }
        }
    }
}

// ---------------- K4: finalize Wd scale ----------------
__global__ void fin2_kernel() {
    int tid = threadIdx.x;
    double s = 0.0;
    for (int i = tid; i < 512; i += 256) s += (double)d_part[2 * 512 + i];
    #pragma unroll
    for (int o = 16; o; o >>= 1) s += __shfl_xor_sync(~0u, s, o);
    __shared__ double ds[8];
    if ((tid & 31) == 0) ds[tid >> 5] = s;
    __syncthreads();
    if (tid == 0) {
        double S = 0.0;
        #pragma unroll
        for (int k = 0; k < 8; k++) S += ds[k];
        d_wsinv[2] = (float)fmax(S / (double)WELEM, 1e-5);
    }
}

// ---------------- K5: v[f] = sum_d ternary(Wd[d,f]) ----------------
__global__ void vsum_kernel(const float* __restrict__ Wd) {
    int f = blockIdx.x * 256 + threadIdx.x;
    int d0 = blockIdx.y * 128;
    float ws = 1.0f / d_wsinv[2];
    float s = 0.f;
    #pragma unroll 4
    for (int d = 0; d < 128; d++)
        s += fminf(fmaxf(rintf(Wd[(size_t)(d0 + d) * FDIM + f] * ws), -1.f), 1.f);
    atomicAdd(&d_v[f], s);
}

// ---------------- K6: rmsnorm + act quant + dot with v ----------------
__global__ void hnorm_kernel(const float* __restrict__ lnw) {
    __shared__ float row[FDIM];
    __shared__ float red[8];
    __shared__ float bval;
    int t = blockIdx.x, tid = threadIdx.x;
    const float* src = d_h + (size_t)t * FDIM;
    float ss = 0.f;
    for (int i = tid; i < FDIM; i += 256) { float v = src[i]; row[i] = v; ss += v * v; }
    ss = wsum(ss);
    if ((tid & 31) == 0) red[tid >> 5] = ss;
    __syncthreads();
    if (tid == 0) {
        float S = 0.f;
        #pragma unroll
        for (int k = 0; k < 8; k++) S += red[k];
        bval = rsqrtf(S / (float)FDIM + 1e-6f);
    }
    __syncthreads();
    float rn = bval, mx = 0.f;
    for (int i = tid; i < FDIM; i += 256) {
        float v = row[i] * rn * lnw[i];
        row[i] = v;
        mx = fmaxf(mx, fabsf(v));
    }
    mx = wmax(mx);
    if ((tid & 31) == 0) red[tid >> 5] = mx;
    __syncthreads();
    if (tid == 0) {
        float M = 0.f;
        #pragma unroll
        for (int k = 0; k < 8; k++) M = fmaxf(M, red[k]);
        bval = fmaxf(M, 1e-5f);
    }
    __syncthreads();
    float clipv = bval, scale = 127.f / clipv, dot = 0.f;
    for (int i = tid; i < FDIM; i += 256) {
        float q = fminf(fmaxf(rintf(row[i] * scale), -128.f), 127.f);
        dot += q * d_v[i];
    }
    dot = wsum(dot);
    if ((tid & 31) == 0) red[tid >> 5] = dot;
    __syncthreads();
    if (tid == 0) {
        float S = 0.f;
        #pragma unroll
        for (int k = 0; k < 8; k++) S += red[k];
        d_tok[t] = S * (clipv / 127.f) * d_wsinv[2];
    }
}

// ---------------- K7: pool ----------------
__global__ void pool_kernel() {
    int g = blockIdx.x, tid = threadIdx.x;
    float v = d_tok[g * 128 + tid];
    v = wsum(v);
    __shared__ float r[4];
    if ((tid & 31) == 0) r[tid >> 5] = v;
    __syncthreads();
    if (tid == 0) d_pool[g] = (r[0] + r[1] + r[2] + r[3]) * (1.0f / (128.f * 2048.f));
}

// ---------------- K8: classifier ----------------
__global__ void cls_kernel(const float* __restrict__ W, const float* __restrict__ b,
                           float* __restrict__ out) {
    int i = blockIdx.x * 256 + threadIdx.x;
    if (i < 8000) {
        int bb = i / 1000, n = i % 1000;
        float s = b[n];
        #pragma unroll
        for (int c = 0; c < 3; c++) s += d_pool[bb * 3 + c] * W[n * 3 + c];
        out[i] = s;
    }
}

extern "C" void kernel_launch(void* const* d_in, const int* in_sizes, int n_in,
                              void* d_out, int out_size) {
    const float* x    = (const float*)d_in[0];
    const float* Wg   = (const float*)d_in[1];
    const float* Wu   = (const float*)d_in[2];
    const float* Wd   = (const float*)d_in[3];
    const float* lnw  = (const float*)d_in[4];
    const float* clsW = (const float*)d_in[5];
    const float* clsb = (const float*)d_in[6];
    float* out = (float*)d_out;

    cudaFuncSetAttribute(gemm_kernel, cudaFuncAttributeMaxDynamicSharedMemorySize, SMEM_GEMM);

    wred_kernel<<<dim3(512, 3), 256>>>(Wg, Wu, Wd);
    qw2_kernel<<<dim3(4096, 2), 256>>>(Wg, Wu);
    act_kernel<<<TOK, 256>>>(x);
    gemm_kernel<<<dim3(FDIM / BN, TOK / BM), 512, SMEM_GEMM>>>();
    fin2_kernel<<<1, 256>>>();
    vsum_kernel<<<dim3(32, 16), 256>>>(Wd);
    hnorm_kernel<<<TOK, 256>>>(lnw);
    pool_kernel<<<24, 128>>>();
    cls_kernel<<<32, 256>>>(clsW, clsb, out);
}

// round 8
// speedup vs baseline: 1.8416x; 1.8416x over previous
#include <cuda_runtime.h>
#include <cuda_bf16.h>
#include <cstdint>
#include <cstddef>

#define DEVFN __device__ __forceinline__

constexpr int TOK = 3072, DDIM = 2048, FDIM = 8192;
constexpr int WELEM = FDIM * DDIM;
constexpr int BM = 128, BN = 128, BK = 64;
constexpr int KITERS = DDIM / BK;            // 32
constexpr int TILE_B = BM * BK;              // 8192 B
constexpr int STAGE_B = 3 * TILE_B;          // 24576
constexpr int STAGES = 4;
constexpr int SMEM_GEMM = STAGES * STAGE_B;  // 98304

__device__ float d_part[3 * 512];
__device__ float d_wsinv[3];
__device__ uint8_t d_qa[(size_t)TOK * DDIM];
__device__ float d_ainv[TOK];
__device__ uint8_t d_qg[(size_t)FDIM * DDIM];
__device__ uint8_t d_qu[(size_t)FDIM * DDIM];
__device__ float d_v[FDIM];
__device__ float d_h[(size_t)TOK * FDIM];
__device__ float d_tok[TOK];
__device__ float d_pool[24];

DEVFN float wsum(float v) {
    #pragma unroll
    for (int o = 16; o; o >>= 1) v += __shfl_xor_sync(~0u, v, o);
    return v;
}
DEVFN float wmax(float v) {
    #pragma unroll
    for (int o = 16; o; o >>= 1) v = fmaxf(v, __shfl_xor_sync(~0u, v, o));
    return v;
}
DEVFN int8_t tern(float w, float ws) {
    return (int8_t)(int)fminf(fmaxf(rintf(w * ws), -1.f), 1.f);
}

// ---------------- K0: |W| partial sums ----------------
__global__ void wred_kernel(const float* __restrict__ Wg, const float* __restrict__ Wu,
                            const float* __restrict__ Wd) {
    int y = blockIdx.y;
    const float4* W = (const float4*)(y == 0 ? Wg : (y == 1 ? Wu : Wd));
    float s = 0.f;
    for (int i = blockIdx.x * 256 + threadIdx.x; i < WELEM / 4; i += 512 * 256) {
        float4 w = W[i];
        s += fabsf(w.x) + fabsf(w.y) + fabsf(w.z) + fabsf(w.w);
    }
    s = wsum(s);
    __shared__ float rs[8];
    if ((threadIdx.x & 31) == 0) rs[threadIdx.x >> 5] = s;
    __syncthreads();
    if (threadIdx.x == 0) {
        float S = 0.f;
        #pragma unroll
        for (int k = 0; k < 8; k++) S += rs[k];
        d_part[y * 512 + blockIdx.x] = S;
    }
}

// packed fragment addressing
DEVFN size_t a_addr(int m, int g) {
    int kb = g >> 4;
    int i4 = (m & 127) >> 4;
    int s = (g >> 3) & 1;
    int t = ((m & 7) << 2) | (g & 3);
    int r = ((m >> 3) & 1) | (((g >> 2) & 1) << 1);
    return ((size_t)((m >> 7) * 32 + kb) << 13) + (((s * 8 + i4) * 32 + t) << 4) + r * 4;
}
DEVFN size_t b_addr(int n, int g) {
    int kb = g >> 4;
    int j = (n & 127) >> 3;
    int s = (g >> 3) & 1;
    int t = ((n & 7) << 2) | (g & 3);
    int r = (g >> 2) & 1;
    return ((size_t)((n >> 7) * 32 + kb) << 13) + (((s * 16 + j) * 32 + t) << 3) + r * 4;
}

// ---------------- K1: ternary quant Wg,Wu (inline scale); zero d_v ----------------
__global__ void qw2_kernel(const float* __restrict__ Wg, const float* __restrict__ Wu) {
    int y = blockIdx.y, tid = threadIdx.x;
    float ps = 0.f;
    #pragma unroll
    for (int k = 0; k < 2; k++) ps += d_part[y * 512 + tid * 2 + k];
    ps = wsum(ps);
    __shared__ float rs[8];
    __shared__ float sws;
    if ((tid & 31) == 0) rs[tid >> 5] = ps;
    __syncthreads();
    if (tid == 0) {
        float S = 0.f;
        #pragma unroll
        for (int k = 0; k < 8; k++) S += rs[k];
        float wm = fmaxf(S / (float)WELEM, 1e-5f);
        sws = wm;
        if (blockIdx.x == 0) d_wsinv[y] = wm;
    }
    __syncthreads();
    if (y == 0 && blockIdx.x < 32) d_v[blockIdx.x * 256 + tid] = 0.f;
    const float4* src = (const float4*)(y ? Wu : Wg);
    uint8_t* dst = y ? d_qu : d_qg;
    float ws = 1.0f / sws;
    int stride = gridDim.x * 256;
    for (int i = blockIdx.x * 256 + tid; i < WELEM / 4; i += stride) {
        int n = i >> 9, g = i & 511;
        float4 w = src[i];
        uint32_t p = (uint32_t)(uint8_t)tern(w.x, ws) |
                     ((uint32_t)(uint8_t)tern(w.y, ws) << 8) |
                     ((uint32_t)(uint8_t)tern(w.z, ws) << 16) |
                     ((uint32_t)(uint8_t)tern(w.w, ws) << 24);
        *(uint32_t*)(dst + b_addr(n, g)) = p;
    }
}

// ---------------- K2: activation quant -> packed int8 ----------------
__global__ void act_kernel(const float* __restrict__ x) {
    int m = blockIdx.x, tid = threadIdx.x;
    const float4* row = (const float4*)(x + (size_t)m * DDIM);
    float mx = 0.f;
    for (int i = tid; i < 512; i += 256) {
        float4 w = row[i];
        mx = fmaxf(mx, fmaxf(fmaxf(fabsf(w.x), fabsf(w.y)), fmaxf(fabsf(w.z), fabsf(w.w))));
    }
    mx = wmax(mx);
    __shared__ float rm[8], smv;
    if ((tid & 31) == 0) rm[tid >> 5] = mx;
    __syncthreads();
    if (tid == 0) {
        float M = 0.f;
        #pragma unroll
        for (int k = 0; k < 8; k++) M = fmaxf(M, rm[k]);
        smv = fmaxf(M, 1e-5f);
    }
    __syncthreads();
    float scale = 127.0f / smv;
    for (int g = tid; g < 512; g += 256) {
        float4 w = row[g];
        int q0 = (int)fminf(fmaxf(rintf(w.x * scale), -128.f), 127.f);
        int q1 = (int)fminf(fmaxf(rintf(w.y * scale), -128.f), 127.f);
        int q2 = (int)fminf(fmaxf(rintf(w.z * scale), -128.f), 127.f);
        int q3 = (int)fminf(fmaxf(rintf(w.w * scale), -128.f), 127.f);
        uint32_t p = (uint32_t)(uint8_t)q0 | ((uint32_t)(uint8_t)q1 << 8) |
                     ((uint32_t)(uint8_t)q2 << 16) | ((uint32_t)(uint8_t)q3 << 24);
        *(uint32_t*)(d_qa + a_addr(m, g)) = p;
    }
    if (tid == 0) d_ainv[m] = smv / 127.0f;
}

// ---------------- K3: hybrid tensor(48 cols)+dp4a(80 cols) double-GEMM ----------------
DEVFN void mma_s8(int* c, const uint32_t* a, uint32_t b0, uint32_t b1) {
    asm volatile(
        "mma.sync.aligned.m16n8k32.row.col.s32.s8.s8.s32 "
        "{%0,%1,%2,%3}, {%4,%5,%6,%7}, {%8,%9}, {%0,%1,%2,%3};"
        : "+r"(c[0]), "+r"(c[1]), "+r"(c[2]), "+r"(c[3])
        : "r"(a[0]), "r"(a[1]), "r"(a[2]), "r"(a[3]), "r"(b0), "r"(b1));
}

DEVFN void stage_copy(uint8_t* smem, int st, const uint8_t* gA, const uint8_t* gG,
                      const uint8_t* gU, int kb, int tid) {
    uint8_t* base = smem + st * STAGE_B;
    size_t koff = (size_t)kb * TILE_B + (size_t)(tid << 4);
    uint32_t d0;
    asm("{ .reg .u64 t; cvta.to.shared.u64 t, %1; cvt.u32.u64 %0, t; }"
        : "=r"(d0) : "l"(base + (tid << 4)));
    asm volatile("cp.async.cg.shared.global [%0], [%1], 16;" :: "r"(d0), "l"(gA + koff));
    asm volatile("cp.async.cg.shared.global [%0], [%1], 16;" :: "r"(d0 + TILE_B), "l"(gG + koff));
    asm volatile("cp.async.cg.shared.global [%0], [%1], 16;" :: "r"(d0 + 2 * TILE_B), "l"(gU + koff));
}

__global__ void __launch_bounds__(512, 1) gemm_kernel() {
    extern __shared__ uint8_t smem[];
    int tid = threadIdx.x, lane = tid & 31, wid = tid >> 5;
    int mb = blockIdx.y, nb = blockIdx.x;

    const uint8_t* gA = d_qa + ((size_t)mb << 18);
    const uint8_t* gG = d_qg + ((size_t)nb << 18);
    const uint8_t* gU = d_qu + ((size_t)nb << 18);

    // tensor warps (wid 0..7): acc[0..47]; dp4a warps (wid 8..15): acc[0..79]
    int acc[80];
    #pragma unroll
    for (int k = 0; k < 80; k++) acc[k] = 0;

    // tensor warp coords: 4m x 2n, n in [0,48)
    int wm = wid & 3, wn = (wid >> 2) & 1;
    // dp4a warp coords (R5-safe mapping): mat x 4 m-blocks, n in [48,128)
    int dw = wid - 8;
    int mat = dw & 1, mblk = dw >> 1;
    int mrow = lane >> 3, ncol = lane & 7;
    int i4 = mblk * 2 + (mrow >> 1);
    int wsel = mrow & 1;            // which word pair of the uint4

    #pragma unroll
    for (int st = 0; st < 3; st++) {
        stage_copy(smem, st, gA, gG, gU, st, tid);
        asm volatile("cp.async.commit_group;" ::: "memory");
    }

    for (int kb = 0; kb < KITERS; kb++) {
        if (kb < 30)       asm volatile("cp.async.wait_group 2;" ::: "memory");
        else if (kb == 30) asm volatile("cp.async.wait_group 1;" ::: "memory");
        else               asm volatile("cp.async.wait_group 0;" ::: "memory");
        __syncthreads();

        if (kb + 3 < KITERS) {
            stage_copy(smem, (kb + 3) & 3, gA, gG, gU, kb + 3, tid);
            asm volatile("cp.async.commit_group;" ::: "memory");
        }

        const uint8_t* sA = smem + (kb & 3) * STAGE_B;
        const uint8_t* sG = sA + TILE_B;
        const uint8_t* sU = sA + 2 * TILE_B;

        if (wid < 8) {
            // -------- tensor path: n in [0,48) --------
            #pragma unroll
            for (int s = 0; s < 2; s++) {
                uint32_t af[2][4];
                #pragma unroll
                for (int mt = 0; mt < 2; mt++) {
                    uint4 v = *(const uint4*)(sA + (((s * 8 + 2 * wm + mt) * 32 + lane) << 4));
                    af[mt][0] = v.x; af[mt][1] = v.y; af[mt][2] = v.z; af[mt][3] = v.w;
                }
                #pragma unroll
                for (int j8 = 0; j8 < 3; j8++) {
                    int j = wn * 3 + j8;
                    uint2 bg = *(const uint2*)(sG + (((s * 16 + j) * 32 + lane) << 3));
                    uint2 bu = *(const uint2*)(sU + (((s * 16 + j) * 32 + lane) << 3));
                    #pragma unroll
                    for (int mt = 0; mt < 2; mt++) {
                        mma_s8(&acc[((mt * 3 + j8) * 2 + 0) * 4], af[mt], bg.x, bg.y);
                        mma_s8(&acc[((mt * 3 + j8) * 2 + 1) * 4], af[mt], bu.x, bu.y);
                    }
                }
            }
        } else {
            // -------- dp4a path: n in [48,128) --------
            const uint8_t* sB = mat ? sU : sG;
            #pragma unroll
            for (int s = 0; s < 2; s++) {
                #pragma unroll
                for (int g2 = 0; g2 < 4; g2++) {
                    int a0 = ((s * 8 + i4) * 32 + g2) << 4;
                    int b0 = (((s * 16 + 6) * 32 + ncol * 4 + g2) << 3);
                    int av0[8], av1[8];
                    #pragma unroll
                    for (int i = 0; i < 8; i++) {
                        uint4 v = *(const uint4*)(sA + a0 + (i << 6));
                        av0[i] = wsel ? (int)v.y : (int)v.x;
                        av1[i] = wsel ? (int)v.w : (int)v.z;
                    }
                    #pragma unroll
                    for (int j = 0; j < 10; j++) {
                        int2 b2 = *(const int2*)(sB + b0 + (j << 8));
                        #pragma unroll
                        for (int i = 0; i < 8; i++)
                            acc[i * 10 + j] = __dp4a(av1[i], b2.y,
                                              __dp4a(av0[i], b2.x, acc[i * 10 + j]));
                    }
                }
            }
        }
    }

    __syncthreads();
    // dp4a G-warps publish int sums (128 rows x 80 cols)
    int* sx = (int*)smem;
    if (wid >= 8 && mat == 0) {
        #pragma unroll
        for (int i = 0; i < 8; i++)
            #pragma unroll
            for (int j = 0; j < 10; j++)
                sx[(mblk * 32 + mrow * 8 + i) * 80 + j * 8 + ncol] = acc[i * 10 + j];
    }
    __syncthreads();

    float wsg = d_wsinv[0], wsu = d_wsinv[1];
    if (wid < 8) {
        // tensor epilogue: n in [0,48)
        #pragma unroll
        for (int mt = 0; mt < 2; mt++) {
            #pragma unroll
            for (int h2 = 0; h2 < 2; h2++) {
                int row = mb * 128 + (2 * wm + mt) * 16 + h2 * 8 + (lane >> 2);
                float ai = d_ainv[row];
                float sg = wsg * ai, su = wsu * ai;
                float* drow = d_h + (size_t)row * FDIM;
                #pragma unroll
                for (int j8 = 0; j8 < 3; j8++) {
                    int n0 = nb * 128 + (wn * 3 + j8) * 8 + 2 * (lane & 3);
                    float g0 = (float)acc[((mt * 3 + j8) * 2 + 0) * 4 + h2 * 2] * sg;
                    float g1 = (float)acc[((mt * 3 + j8) * 2 + 0) * 4 + h2 * 2 + 1] * sg;
                    float u0 = (float)acc[((mt * 3 + j8) * 2 + 1) * 4 + h2 * 2] * su;
                    float u1 = (float)acc[((mt * 3 + j8) * 2 + 1) * 4 + h2 * 2 + 1] * su;
                    float2 o;
                    o.x = g0 / (1.f + __expf(-g0)) * u0;
                    o.y = g1 / (1.f + __expf(-g1)) * u1;
                    *(float2*)(drow + n0) = o;
                }
            }
        }
    } else if (mat == 1) {
        // dp4a combine epilogue: n in [48,128)
        #pragma unroll
        for (int i = 0; i < 8; i++) {
            int row = mb * 128 + mblk * 32 + mrow * 8 + i;
            float ai = d_ainv[row];
            float sg = wsg * ai, su = wsu * ai;
            float* drow = d_h + (size_t)row * FDIM + nb * 128 + 48;
            #pragma unroll
            for (int j = 0; j < 10; j++) {
                float g = (float)sx[(mblk * 32 + mrow * 8 + i) * 80 + j * 8 + ncol] * sg;
                float u = (float)acc[i * 10 + j] * su;
                drow[j * 8 + ncol] = g / (1.f + __expf(-g)) * u;
            }
        }
    }
}

// ---------------- K4: finalize Wd scale ----------------
__global__ void fin2_kernel() {
    int tid = threadIdx.x;
    double s = 0.0;
    for (int i = tid; i < 512; i += 256) s += (double)d_part[2 * 512 + i];
    #pragma unroll
    for (int o = 16; o; o >>= 1) s += __shfl_xor_sync(~0u, s, o);
    __shared__ double ds[8];
    if ((tid & 31) == 0) ds[tid >> 5] = s;
    __syncthreads();
    if (tid == 0) {
        double S = 0.0;
        #pragma unroll
        for (int k = 0; k < 8; k++) S += ds[k];
        d_wsinv[2] = (float)fmax(S / (double)WELEM, 1e-5);
    }
}

// ---------------- K5: v[f] = sum_d ternary(Wd[d,f]) ----------------
__global__ void vsum_kernel(const float* __restrict__ Wd) {
    int f = blockIdx.x * 256 + threadIdx.x;
    int d0 = blockIdx.y * 128;
    float ws = 1.0f / d_wsinv[2];
    float s = 0.f;
    #pragma unroll 4
    for (int d = 0; d < 128; d++)
        s += fminf(fmaxf(rintf(Wd[(size_t)(d0 + d) * FDIM + f] * ws), -1.f), 1.f);
    atomicAdd(&d_v[f], s);
}

// ---------------- K6: rmsnorm + act quant + dot with v ----------------
__global__ void hnorm_kernel(const float* __restrict__ lnw) {
    __shared__ float row[FDIM];
    __shared__ float red[8];
    __shared__ float bval;
    int t = blockIdx.x, tid = threadIdx.x;
    const float* src = d_h + (size_t)t * FDIM;
    float ss = 0.f;
    for (int i = tid; i < FDIM; i += 256) { float v = src[i]; row[i] = v; ss += v * v; }
    ss = wsum(ss);
    if ((tid & 31) == 0) red[tid >> 5] = ss;
    __syncthreads();
    if (tid == 0) {
        float S = 0.f;
        #pragma unroll
        for (int k = 0; k < 8; k++) S += red[k];
        bval = rsqrtf(S / (float)FDIM + 1e-6f);
    }
    __syncthreads();
    float rn = bval, mx = 0.f;
    for (int i = tid; i < FDIM; i += 256) {
        float v = row[i] * rn * lnw[i];
        row[i] = v;
        mx = fmaxf(mx, fabsf(v));
    }
    mx = wmax(mx);
    if ((tid & 31) == 0) red[tid >> 5] = mx;
    __syncthreads();
    if (tid == 0) {
        float M = 0.f;
        #pragma unroll
        for (int k = 0; k < 8; k++) M = fmaxf(M, red[k]);
        bval = fmaxf(M, 1e-5f);
    }
    __syncthreads();
    float clipv = bval, scale = 127.f / clipv, dot = 0.f;
    for (int i = tid; i < FDIM; i += 256) {
        float q = fminf(fmaxf(rintf(row[i] * scale), -128.f), 127.f);
        dot += q * d_v[i];
    }
    dot = wsum(dot);
    if ((tid & 31) == 0) red[tid >> 5] = dot;
    __syncthreads();
    if (tid == 0) {
        float S = 0.f;
        #pragma unroll
        for (int k = 0; k < 8; k++) S += red[k];
        d_tok[t] = S * (clipv / 127.f) * d_wsinv[2];
    }
}

// ---------------- K7: pool ----------------
__global__ void pool_kernel() {
    int g = blockIdx.x, tid = threadIdx.x;
    float v = d_tok[g * 128 + tid];
    v = wsum(v);
    __shared__ float r[4];
    if ((tid & 31) == 0) r[tid >> 5] = v;
    __syncthreads();
    if (tid == 0) d_pool[g] = (r[0] + r[1] + r[2] + r[3]) * (1.0f / (128.f * 2048.f));
}

// ---------------- K8: classifier ----------------
__global__ void cls_kernel(const float* __restrict__ W, const float* __restrict__ b,
                           float* __restrict__ out) {
    int i = blockIdx.x * 256 + threadIdx.x;
    if (i < 8000) {
        int bb = i / 1000, n = i % 1000;
        float s = b[n];
        #pragma unroll
        for (int c = 0; c < 3; c++) s += d_pool[bb * 3 + c] * W[n * 3 + c];
        out[i] = s;
    }
}

extern "C" void kernel_launch(void* const* d_in, const int* in_sizes, int n_in,
                              void* d_out, int out_size) {
    const float* x    = (const float*)d_in[0];
    const float* Wg   = (const float*)d_in[1];
    const float* Wu   = (const float*)d_in[2];
    const float* Wd   = (const float*)d_in[3];
    const float* lnw  = (const float*)d_in[4];
    const float* clsW = (const float*)d_in[5];
    const float* clsb = (const float*)d_in[6];
    float* out = (float*)d_out;

    cudaFuncSetAttribute(gemm_kernel, cudaFuncAttributeMaxDynamicSharedMemorySize, SMEM_GEMM);

    wred_kernel<<<dim3(512, 3), 256>>>(Wg, Wu, Wd);
    qw2_kernel<<<dim3(4096, 2), 256>>>(Wg, Wu);
    act_kernel<<<TOK, 256>>>(x);
    gemm_kernel<<<dim3(FDIM / BN, TOK / BM), 512, SMEM_GEMM>>>();
    fin2_kernel<<<1, 256>>>();
    vsum_kernel<<<dim3(32, 16), 256>>>(Wd);
    hnorm_kernel<<<TOK, 256>>>(lnw);
    pool_kernel<<<24, 128>>>();
    cls_kernel<<<32, 256>>>(clsW, clsb, out);
}

// round 9
// speedup vs baseline: 1.8669x; 1.0137x over previous
#include <cuda_runtime.h>
#include <cuda_bf16.h>
#include <cstdint>
#include <cstddef>

#define DEVFN __device__ __forceinline__

constexpr int TOK = 3072, DDIM = 2048, FDIM = 8192;
constexpr int WELEM = FDIM * DDIM;
constexpr int BM = 128, BN = 128, BK = 64;
constexpr int KITERS = DDIM / BK;            // 32
constexpr int TILE_B = BM * BK;              // 8192 B
constexpr int STAGE_B = 3 * TILE_B;          // 24576
constexpr int STAGES = 4;
constexpr int SMEM_GEMM = STAGES * STAGE_B;  // 98304

__device__ float d_part[3 * 512];
__device__ float d_wsinv[3];
__device__ uint8_t d_qa[(size_t)TOK * DDIM];
__device__ float d_ainv[TOK];
__device__ uint8_t d_qg[(size_t)FDIM * DDIM];
__device__ uint8_t d_qu[(size_t)FDIM * DDIM];
__device__ float d_v[FDIM];
__device__ float d_h[(size_t)TOK * FDIM];
__device__ float d_tok[TOK];
__device__ float d_pool[24];

DEVFN float wsum(float v) {
    #pragma unroll
    for (int o = 16; o; o >>= 1) v += __shfl_xor_sync(~0u, v, o);
    return v;
}
DEVFN float wmax(float v) {
    #pragma unroll
    for (int o = 16; o; o >>= 1) v = fmaxf(v, __shfl_xor_sync(~0u, v, o));
    return v;
}
DEVFN int8_t tern(float w, float ws) {
    return (int8_t)(int)fminf(fmaxf(rintf(w * ws), -1.f), 1.f);
}
#define BARRIER() asm volatile("bar.sync 0, 512;" ::: "memory")

// ---------------- K0: |W| partial sums ----------------
__global__ void wred_kernel(const float* __restrict__ Wg, const float* __restrict__ Wu,
                            const float* __restrict__ Wd) {
    int y = blockIdx.y;
    const float4* W = (const float4*)(y == 0 ? Wg : (y == 1 ? Wu : Wd));
    float s = 0.f;
    for (int i = blockIdx.x * 256 + threadIdx.x; i < WELEM / 4; i += 512 * 256) {
        float4 w = W[i];
        s += fabsf(w.x) + fabsf(w.y) + fabsf(w.z) + fabsf(w.w);
    }
    s = wsum(s);
    __shared__ float rs[8];
    if ((threadIdx.x & 31) == 0) rs[threadIdx.x >> 5] = s;
    __syncthreads();
    if (threadIdx.x == 0) {
        float S = 0.f;
        #pragma unroll
        for (int k = 0; k < 8; k++) S += rs[k];
        d_part[y * 512 + blockIdx.x] = S;
    }
}

// packed fragment addressing
DEVFN size_t a_addr(int m, int g) {
    int kb = g >> 4;
    int i4 = (m & 127) >> 4;
    int s = (g >> 3) & 1;
    int t = ((m & 7) << 2) | (g & 3);
    int r = ((m >> 3) & 1) | (((g >> 2) & 1) << 1);
    return ((size_t)((m >> 7) * 32 + kb) << 13) + (((s * 8 + i4) * 32 + t) << 4) + r * 4;
}
DEVFN size_t b_addr(int n, int g) {
    int kb = g >> 4;
    int j = (n & 127) >> 3;
    int s = (g >> 3) & 1;
    int t = ((n & 7) << 2) | (g & 3);
    int r = (g >> 2) & 1;
    return ((size_t)((n >> 7) * 32 + kb) << 13) + (((s * 16 + j) * 32 + t) << 3) + r * 4;
}

// ---------------- K1: ternary quant Wg,Wu (inline scale); zero d_v ----------------
__global__ void qw2_kernel(const float* __restrict__ Wg, const float* __restrict__ Wu) {
    int y = blockIdx.y, tid = threadIdx.x;
    float ps = 0.f;
    #pragma unroll
    for (int k = 0; k < 2; k++) ps += d_part[y * 512 + tid * 2 + k];
    ps = wsum(ps);
    __shared__ float rs[8];
    __shared__ float sws;
    if ((tid & 31) == 0) rs[tid >> 5] = ps;
    __syncthreads();
    if (tid == 0) {
        float S = 0.f;
        #pragma unroll
        for (int k = 0; k < 8; k++) S += rs[k];
        float wm = fmaxf(S / (float)WELEM, 1e-5f);
        sws = wm;
        if (blockIdx.x == 0) d_wsinv[y] = wm;
    }
    __syncthreads();
    if (y == 0 && blockIdx.x < 32) d_v[blockIdx.x * 256 + tid] = 0.f;
    const float4* src = (const float4*)(y ? Wu : Wg);
    uint8_t* dst = y ? d_qu : d_qg;
    float ws = 1.0f / sws;
    int stride = gridDim.x * 256;
    for (int i = blockIdx.x * 256 + tid; i < WELEM / 4; i += stride) {
        int n = i >> 9, g = i & 511;
        float4 w = src[i];
        uint32_t p = (uint32_t)(uint8_t)tern(w.x, ws) |
                     ((uint32_t)(uint8_t)tern(w.y, ws) << 8) |
                     ((uint32_t)(uint8_t)tern(w.z, ws) << 16) |
                     ((uint32_t)(uint8_t)tern(w.w, ws) << 24);
        *(uint32_t*)(dst + b_addr(n, g)) = p;
    }
}

// ---------------- K2: activation quant -> packed int8 ----------------
__global__ void act_kernel(const float* __restrict__ x) {
    int m = blockIdx.x, tid = threadIdx.x;
    const float4* row = (const float4*)(x + (size_t)m * DDIM);
    float mx = 0.f;
    for (int i = tid; i < 512; i += 256) {
        float4 w = row[i];
        mx = fmaxf(mx, fmaxf(fmaxf(fabsf(w.x), fabsf(w.y)), fmaxf(fabsf(w.z), fabsf(w.w))));
    }
    mx = wmax(mx);
    __shared__ float rm[8], smv;
    if ((tid & 31) == 0) rm[tid >> 5] = mx;
    __syncthreads();
    if (tid == 0) {
        float M = 0.f;
        #pragma unroll
        for (int k = 0; k < 8; k++) M = fmaxf(M, rm[k]);
        smv = fmaxf(M, 1e-5f);
    }
    __syncthreads();
    float scale = 127.0f / smv;
    for (int g = tid; g < 512; g += 256) {
        float4 w = row[g];
        int q0 = (int)fminf(fmaxf(rintf(w.x * scale), -128.f), 127.f);
        int q1 = (int)fminf(fmaxf(rintf(w.y * scale), -128.f), 127.f);
        int q2 = (int)fminf(fmaxf(rintf(w.z * scale), -128.f), 127.f);
        int q3 = (int)fminf(fmaxf(rintf(w.w * scale), -128.f), 127.f);
        uint32_t p = (uint32_t)(uint8_t)q0 | ((uint32_t)(uint8_t)q1 << 8) |
                     ((uint32_t)(uint8_t)q2 << 16) | ((uint32_t)(uint8_t)q3 << 24);
        *(uint32_t*)(d_qa + a_addr(m, g)) = p;
    }
    if (tid == 0) d_ainv[m] = smv / 127.0f;
}

// ---------------- K3: hybrid tensor(48)+dp4a(80) double-GEMM, split loops ----------------
DEVFN void mma_s8(int* c, const uint32_t* a, uint32_t b0, uint32_t b1) {
    asm volatile(
        "mma.sync.aligned.m16n8k32.row.col.s32.s8.s8.s32 "
        "{%0,%1,%2,%3}, {%4,%5,%6,%7}, {%8,%9}, {%0,%1,%2,%3};"
        : "+r"(c[0]), "+r"(c[1]), "+r"(c[2]), "+r"(c[3])
        : "r"(a[0]), "r"(a[1]), "r"(a[2]), "r"(a[3]), "r"(b0), "r"(b1));
}

DEVFN void stage_copy(uint8_t* smem, int st, const uint8_t* gA, const uint8_t* gG,
                      const uint8_t* gU, int kb, int tid) {
    uint8_t* base = smem + st * STAGE_B;
    size_t koff = (size_t)kb * TILE_B + (size_t)(tid << 4);
    uint32_t d0;
    asm("{ .reg .u64 t; cvta.to.shared.u64 t, %1; cvt.u32.u64 %0, t; }"
        : "=r"(d0) : "l"(base + (tid << 4)));
    asm volatile("cp.async.cg.shared.global [%0], [%1], 16;" :: "r"(d0), "l"(gA + koff));
    asm volatile("cp.async.cg.shared.global [%0], [%1], 16;" :: "r"(d0 + TILE_B), "l"(gG + koff));
    asm volatile("cp.async.cg.shared.global [%0], [%1], 16;" :: "r"(d0 + 2 * TILE_B), "l"(gU + koff));
}

#define PIPE_WAIT(kb) do { \
    if ((kb) < 30)       asm volatile("cp.async.wait_group 2;" ::: "memory"); \
    else if ((kb) == 30) asm volatile("cp.async.wait_group 1;" ::: "memory"); \
    else                 asm volatile("cp.async.wait_group 0;" ::: "memory"); \
} while (0)

__global__ void __launch_bounds__(512, 1) gemm_kernel() {
    extern __shared__ uint8_t smem[];
    int tid = threadIdx.x, lane = tid & 31, wid = tid >> 5;
    int mb = blockIdx.y, nb = blockIdx.x;

    const uint8_t* gA = d_qa + ((size_t)mb << 18);
    const uint8_t* gG = d_qg + ((size_t)nb << 18);
    const uint8_t* gU = d_qu + ((size_t)nb << 18);

    #pragma unroll
    for (int st = 0; st < 3; st++) {
        stage_copy(smem, st, gA, gG, gU, st, tid);
        asm volatile("cp.async.commit_group;" ::: "memory");
    }

    float wsg = d_wsinv[0], wsu = d_wsinv[1];
    int* sx = (int*)smem;

    if (wid < 8) {
        // ================= tensor warps: n in [0,48) =================
        int wm = wid & 3, wn = (wid >> 2) & 1;
        int acc[48];
        #pragma unroll
        for (int k = 0; k < 48; k++) acc[k] = 0;

        for (int kb = 0; kb < KITERS; kb++) {
            PIPE_WAIT(kb);
            BARRIER();
            if (kb + 3 < KITERS) {
                stage_copy(smem, (kb + 3) & 3, gA, gG, gU, kb + 3, tid);
                asm volatile("cp.async.commit_group;" ::: "memory");
            }
            const uint8_t* sA = smem + (kb & 3) * STAGE_B;
            const uint8_t* sG = sA + TILE_B;
            const uint8_t* sU = sA + 2 * TILE_B;
            #pragma unroll
            for (int s = 0; s < 2; s++) {
                uint32_t af[2][4];
                #pragma unroll
                for (int mt = 0; mt < 2; mt++) {
                    uint4 v = *(const uint4*)(sA + (((s * 8 + 2 * wm + mt) * 32 + lane) << 4));
                    af[mt][0] = v.x; af[mt][1] = v.y; af[mt][2] = v.z; af[mt][3] = v.w;
                }
                #pragma unroll
                for (int j8 = 0; j8 < 3; j8++) {
                    int j = wn * 3 + j8;
                    uint2 bg = *(const uint2*)(sG + (((s * 16 + j) * 32 + lane) << 3));
                    uint2 bu = *(const uint2*)(sU + (((s * 16 + j) * 32 + lane) << 3));
                    #pragma unroll
                    for (int mt = 0; mt < 2; mt++) {
                        mma_s8(&acc[((mt * 3 + j8) * 2 + 0) * 4], af[mt], bg.x, bg.y);
                        mma_s8(&acc[((mt * 3 + j8) * 2 + 1) * 4], af[mt], bu.x, bu.y);
                    }
                }
            }
        }
        BARRIER();  // A: all compute done
        BARRIER();  // B: sx published (by dp4a G warps)
        #pragma unroll
        for (int mt = 0; mt < 2; mt++) {
            #pragma unroll
            for (int h2 = 0; h2 < 2; h2++) {
                int row = mb * 128 + (2 * wm + mt) * 16 + h2 * 8 + (lane >> 2);
                float ai = d_ainv[row];
                float sg = wsg * ai, su = wsu * ai;
                float* drow = d_h + (size_t)row * FDIM;
                #pragma unroll
                for (int j8 = 0; j8 < 3; j8++) {
                    int n0 = nb * 128 + (wn * 3 + j8) * 8 + 2 * (lane & 3);
                    float g0 = (float)acc[((mt * 3 + j8) * 2 + 0) * 4 + h2 * 2] * sg;
                    float g1 = (float)acc[((mt * 3 + j8) * 2 + 0) * 4 + h2 * 2 + 1] * sg;
                    float u0 = (float)acc[((mt * 3 + j8) * 2 + 1) * 4 + h2 * 2] * su;
                    float u1 = (float)acc[((mt * 3 + j8) * 2 + 1) * 4 + h2 * 2 + 1] * su;
                    float2 o;
                    o.x = g0 / (1.f + __expf(-g0)) * u0;
                    o.y = g1 / (1.f + __expf(-g1)) * u1;
                    *(float2*)(drow + n0) = o;
                }
            }
        }
    } else {
        // ================= dp4a warps: n in [48,128) =================
        int dw = wid - 8;
        int mat = dw & 1, mblk = dw >> 1;
        int mrow = lane >> 3, ncol = lane & 7;
        int i4 = mblk * 2 + (mrow >> 1);
        int r0 = (mrow & 1) * 4;
        int acc[80];
        #pragma unroll
        for (int k = 0; k < 80; k++) acc[k] = 0;

        for (int kb = 0; kb < KITERS; kb++) {
            PIPE_WAIT(kb);
            BARRIER();
            if (kb + 3 < KITERS) {
                stage_copy(smem, (kb + 3) & 3, gA, gG, gU, kb + 3, tid);
                asm volatile("cp.async.commit_group;" ::: "memory");
            }
            const uint8_t* sA = smem + (kb & 3) * STAGE_B;
            const uint8_t* sB = sA + TILE_B + (mat ? TILE_B : 0);
            #pragma unroll
            for (int s = 0; s < 2; s++) {
                #pragma unroll
                for (int g2 = 0; g2 < 4; g2++) {
                    int b0 = (((s * 16 + 6) * 32 + ncol * 4 + g2) << 3);
                    int bv0[10], bv1[10];
                    #pragma unroll
                    for (int j = 0; j < 10; j++) {
                        int2 b2 = *(const int2*)(sB + b0 + (j << 8));
                        bv0[j] = b2.x; bv1[j] = b2.y;
                    }
                    int a0 = (((s * 8 + i4) * 32 + g2) << 4) + r0;
                    #pragma unroll
                    for (int i = 0; i < 8; i++) {
                        const uint8_t* p = sA + a0 + (i << 6);
                        int av0 = *(const int*)p;
                        int av1 = *(const int*)(p + 8);
                        #pragma unroll
                        for (int j = 0; j < 10; j++)
                            acc[i * 10 + j] = __dp4a(av1, bv1[j],
                                              __dp4a(av0, bv0[j], acc[i * 10 + j]));
                    }
                }
            }
        }
        BARRIER();  // A
        if (mat == 0) {
            #pragma unroll
            for (int i = 0; i < 8; i++)
                #pragma unroll
                for (int j = 0; j < 10; j++)
                    sx[(mblk * 32 + mrow * 8 + i) * 80 + j * 8 + ncol] = acc[i * 10 + j];
        }
        BARRIER();  // B
        if (mat == 1) {
            #pragma unroll
            for (int i = 0; i < 8; i++) {
                int row = mb * 128 + mblk * 32 + mrow * 8 + i;
                float ai = d_ainv[row];
                float sg = wsg * ai, su = wsu * ai;
                float* drow = d_h + (size_t)row * FDIM + nb * 128 + 48;
                #pragma unroll
                for (int j = 0; j < 10; j++) {
                    float g = (float)sx[(mblk * 32 + mrow * 8 + i) * 80 + j * 8 + ncol] * sg;
                    float u = (float)acc[i * 10 + j] * su;
                    drow[j * 8 + ncol] = g / (1.f + __expf(-g)) * u;
                }
            }
        }
    }
}

// ---------------- K4: finalize Wd scale ----------------
__global__ void fin2_kernel() {
    int tid = threadIdx.x;
    double s = 0.0;
    for (int i = tid; i < 512; i += 256) s += (double)d_part[2 * 512 + i];
    #pragma unroll
    for (int o = 16; o; o >>= 1) s += __shfl_xor_sync(~0u, s, o);
    __shared__ double ds[8];
    if ((tid & 31) == 0) ds[tid >> 5] = s;
    __syncthreads();
    if (tid == 0) {
        double S = 0.0;
        #pragma unroll
        for (int k = 0; k < 8; k++) S += ds[k];
        d_wsinv[2] = (float)fmax(S / (double)WELEM, 1e-5);
    }
}

// ---------------- K5: v[f] = sum_d ternary(Wd[d,f]) ----------------
__global__ void vsum_kernel(const float* __restrict__ Wd) {
    int f = blockIdx.x * 256 + threadIdx.x;
    int d0 = blockIdx.y * 128;
    float ws = 1.0f / d_wsinv[2];
    float s = 0.f;
    #pragma unroll 4
    for (int d = 0; d < 128; d++)
        s += fminf(fmaxf(rintf(Wd[(size_t)(d0 + d) * FDIM + f] * ws), -1.f), 1.f);
    atomicAdd(&d_v[f], s);
}

// ---------------- K6: rmsnorm + act quant + dot with v ----------------
__global__ void hnorm_kernel(const float* __restrict__ lnw) {
    __shared__ float row[FDIM];
    __shared__ float red[8];
    __shared__ float bval;
    int t = blockIdx.x, tid = threadIdx.x;
    const float* src = d_h + (size_t)t * FDIM;
    float ss = 0.f;
    for (int i = tid; i < FDIM; i += 256) { float v = src[i]; row[i] = v; ss += v * v; }
    ss = wsum(ss);
    if ((tid & 31) == 0) red[tid >> 5] = ss;
    __syncthreads();
    if (tid == 0) {
        float S = 0.f;
        #pragma unroll
        for (int k = 0; k < 8; k++) S += red[k];
        bval = rsqrtf(S / (float)FDIM + 1e-6f);
    }
    __syncthreads();
    float rn = bval, mx = 0.f;
    for (int i = tid; i < FDIM; i += 256) {
        float v = row[i] * rn * lnw[i];
        row[i] = v;
        mx = fmaxf(mx, fabsf(v));
    }
    mx = wmax(mx);
    if ((tid & 31) == 0) red[tid >> 5] = mx;
    __syncthreads();
    if (tid == 0) {
        float M = 0.f;
        #pragma unroll
        for (int k = 0; k < 8; k++) M = fmaxf(M, red[k]);
        bval = fmaxf(M, 1e-5f);
    }
    __syncthreads();
    float clipv = bval, scale = 127.f / clipv, dot = 0.f;
    for (int i = tid; i < FDIM; i += 256) {
        float q = fminf(fmaxf(rintf(row[i] * scale), -128.f), 127.f);
        dot += q * d_v[i];
    }
    dot = wsum(dot);
    if ((tid & 31) == 0) red[tid >> 5] = dot;
    __syncthreads();
    if (tid == 0) {
        float S = 0.f;
        #pragma unroll
        for (int k = 0; k < 8; k++) S += red[k];
        d_tok[t] = S * (clipv / 127.f) * d_wsinv[2];
    }
}

// ---------------- K7: pool ----------------
__global__ void pool_kernel() {
    int g = blockIdx.x, tid = threadIdx.x;
    float v = d_tok[g * 128 + tid];
    v = wsum(v);
    __shared__ float r[4];
    if ((tid & 31) == 0) r[tid >> 5] = v;
    __syncthreads();
    if (tid == 0) d_pool[g] = (r[0] + r[1] + r[2] + r[3]) * (1.0f / (128.f * 2048.f));
}

// ---------------- K8: classifier ----------------
__global__ void cls_kernel(const float* __restrict__ W, const float* __restrict__ b,
                           float* __restrict__ out) {
    int i = blockIdx.x * 256 + threadIdx.x;
    if (i < 8000) {
        int bb = i / 1000, n = i % 1000;
        float s = b[n];
        #pragma unroll
        for (int c = 0; c < 3; c++) s += d_pool[bb * 3 + c] * W[n * 3 + c];
        out[i] = s;
    }
}

extern "C" void kernel_launch(void* const* d_in, const int* in_sizes, int n_in,
                              void* d_out, int out_size) {
    const float* x    = (const float*)d_in[0];
    const float* Wg   = (const float*)d_in[1];
    const float* Wu   = (const float*)d_in[2];
    const float* Wd   = (const float*)d_in[3];
    const float* lnw  = (const float*)d_in[4];
    const float* clsW = (const float*)d_in[5];
    const float* clsb = (const float*)d_in[6];
    float* out = (float*)d_out;

    cudaFuncSetAttribute(gemm_kernel, cudaFuncAttributeMaxDynamicSharedMemorySize, SMEM_GEMM);

    wred_kernel<<<dim3(512, 3), 256>>>(Wg, Wu, Wd);
    qw2_kernel<<<dim3(4096, 2), 256>>>(Wg, Wu);
    act_kernel<<<TOK, 256>>>(x);
    gemm_kernel<<<dim3(FDIM / BN, TOK / BM), 512, SMEM_GEMM>>>();
    fin2_kernel<<<1, 256>>>();
    vsum_kernel<<<dim3(32, 16), 256>>>(Wd);
    hnorm_kernel<<<TOK, 256>>>(lnw);
    pool_kernel<<<24, 128>>>();
    cls_kernel<<<32, 256>>>(clsW, clsb, out);
}

// round 10
// speedup vs baseline: 2.3777x; 1.2736x over previous
#include <cuda_runtime.h>
#include <cuda_bf16.h>
#include <cstdint>
#include <cstddef>

#define DEVFN __device__ __forceinline__

constexpr int TOK = 3072, DDIM = 2048, FDIM = 8192;
constexpr int WELEM = FDIM * DDIM;
constexpr int BM = 64, BN = 128, BK = 64;
constexpr int KITERS = DDIM / BK;            // 32
constexpr int A_B = BM * BK;                 // 4096
constexpr int W_B = BN * BK;                 // 8192
constexpr int STAGE_B = A_B + 2 * W_B;       // 20480
constexpr int STAGES = 4;
constexpr int SMEM_GEMM = STAGES * STAGE_B;  // 81920

__device__ float d_part[3 * 512];
__device__ float d_wsinv[3];
__device__ uint8_t d_qa[(size_t)TOK * DDIM];
__device__ float d_ainv[TOK];
__device__ uint8_t d_qg[(size_t)FDIM * DDIM];
__device__ uint8_t d_qu[(size_t)FDIM * DDIM];
__device__ float d_v[FDIM];
__device__ float d_h[(size_t)TOK * FDIM];
__device__ float d_tok[TOK];
__device__ float d_pool[24];

DEVFN float wsum(float v) {
    #pragma unroll
    for (int o = 16; o; o >>= 1) v += __shfl_xor_sync(~0u, v, o);
    return v;
}
DEVFN float wmax(float v) {
    #pragma unroll
    for (int o = 16; o; o >>= 1) v = fmaxf(v, __shfl_xor_sync(~0u, v, o));
    return v;
}
DEVFN int8_t tern(float w, float ws) {
    return (int8_t)(int)fminf(fmaxf(rintf(w * ws), -1.f), 1.f);
}

// ---------------- K0: |W| partial sums ----------------
__global__ void wred_kernel(const float* __restrict__ Wg, const float* __restrict__ Wu,
                            const float* __restrict__ Wd) {
    int y = blockIdx.y;
    const float4* W = (const float4*)(y == 0 ? Wg : (y == 1 ? Wu : Wd));
    float s = 0.f;
    for (int i = blockIdx.x * 256 + threadIdx.x; i < WELEM / 4; i += 512 * 256) {
        float4 w = W[i];
        s += fabsf(w.x) + fabsf(w.y) + fabsf(w.z) + fabsf(w.w);
    }
    s = wsum(s);
    __shared__ float rs[8];
    if ((threadIdx.x & 31) == 0) rs[threadIdx.x >> 5] = s;
    __syncthreads();
    if (threadIdx.x == 0) {
        float S = 0.f;
        #pragma unroll
        for (int k = 0; k < 8; k++) S += rs[k];
        d_part[y * 512 + blockIdx.x] = S;
    }
}

// packed fragment addressing (128-row major blocks)
DEVFN size_t a_addr(int m, int g) {
    int kb = g >> 4;
    int i4 = (m & 127) >> 4;
    int s = (g >> 3) & 1;
    int t = ((m & 7) << 2) | (g & 3);
    int r = ((m >> 3) & 1) | (((g >> 2) & 1) << 1);
    return ((size_t)((m >> 7) * 32 + kb) << 13) + (((s * 8 + i4) * 32 + t) << 4) + r * 4;
}
DEVFN size_t b_addr(int n, int g) {
    int kb = g >> 4;
    int j = (n & 127) >> 3;
    int s = (g >> 3) & 1;
    int t = ((n & 7) << 2) | (g & 3);
    int r = (g >> 2) & 1;
    return ((size_t)((n >> 7) * 32 + kb) << 13) + (((s * 16 + j) * 32 + t) << 3) + r * 4;
}

// ---------------- K1: ternary quant Wg,Wu (inline scale); zero d_v ----------------
__global__ void qw2_kernel(const float* __restrict__ Wg, const float* __restrict__ Wu) {
    int y = blockIdx.y, tid = threadIdx.x;
    float ps = 0.f;
    #pragma unroll
    for (int k = 0; k < 2; k++) ps += d_part[y * 512 + tid * 2 + k];
    ps = wsum(ps);
    __shared__ float rs[8];
    __shared__ float sws;
    if ((tid & 31) == 0) rs[tid >> 5] = ps;
    __syncthreads();
    if (tid == 0) {
        float S = 0.f;
        #pragma unroll
        for (int k = 0; k < 8; k++) S += rs[k];
        float wm = fmaxf(S / (float)WELEM, 1e-5f);
        sws = wm;
        if (blockIdx.x == 0) d_wsinv[y] = wm;
    }
    __syncthreads();
    if (y == 0 && blockIdx.x < 32) d_v[blockIdx.x * 256 + tid] = 0.f;
    const float4* src = (const float4*)(y ? Wu : Wg);
    uint8_t* dst = y ? d_qu : d_qg;
    float ws = 1.0f / sws;
    int stride = gridDim.x * 256;
    for (int i = blockIdx.x * 256 + tid; i < WELEM / 4; i += stride) {
        int n = i >> 9, g = i & 511;
        float4 w = src[i];
        uint32_t p = (uint32_t)(uint8_t)tern(w.x, ws) |
                     ((uint32_t)(uint8_t)tern(w.y, ws) << 8) |
                     ((uint32_t)(uint8_t)tern(w.z, ws) << 16) |
                     ((uint32_t)(uint8_t)tern(w.w, ws) << 24);
        *(uint32_t*)(dst + b_addr(n, g)) = p;
    }
}

// ---------------- K2: activation quant -> packed int8 ----------------
__global__ void act_kernel(const float* __restrict__ x) {
    int m = blockIdx.x, tid = threadIdx.x;
    const float4* row = (const float4*)(x + (size_t)m * DDIM);
    float mx = 0.f;
    for (int i = tid; i < 512; i += 256) {
        float4 w = row[i];
        mx = fmaxf(mx, fmaxf(fmaxf(fabsf(w.x), fabsf(w.y)), fmaxf(fabsf(w.z), fabsf(w.w))));
    }
    mx = wmax(mx);
    __shared__ float rm[8], smv;
    if ((tid & 31) == 0) rm[tid >> 5] = mx;
    __syncthreads();
    if (tid == 0) {
        float M = 0.f;
        #pragma unroll
        for (int k = 0; k < 8; k++) M = fmaxf(M, rm[k]);
        smv = fmaxf(M, 1e-5f);
    }
    __syncthreads();
    float scale = 127.0f / smv;
    for (int g = tid; g < 512; g += 256) {
        float4 w = row[g];
        int q0 = (int)fminf(fmaxf(rintf(w.x * scale), -128.f), 127.f);
        int q1 = (int)fminf(fmaxf(rintf(w.y * scale), -128.f), 127.f);
        int q2 = (int)fminf(fmaxf(rintf(w.z * scale), -128.f), 127.f);
        int q3 = (int)fminf(fmaxf(rintf(w.w * scale), -128.f), 127.f);
        uint32_t p = (uint32_t)(uint8_t)q0 | ((uint32_t)(uint8_t)q1 << 8) |
                     ((uint32_t)(uint8_t)q2 << 16) | ((uint32_t)(uint8_t)q3 << 24);
        *(uint32_t*)(d_qa + a_addr(m, g)) = p;
    }
    if (tid == 0) d_ainv[m] = smv / 127.0f;
}

// ---------------- K3: hybrid GEMM, BM=64, 256 thr, 2 CTAs/SM ----------------
DEVFN void mma_s8(int* c, const uint32_t* a, uint32_t b0, uint32_t b1) {
    asm volatile(
        "mma.sync.aligned.m16n8k32.row.col.s32.s8.s8.s32 "
        "{%0,%1,%2,%3}, {%4,%5,%6,%7}, {%8,%9}, {%0,%1,%2,%3};"
        : "+r"(c[0]), "+r"(c[1]), "+r"(c[2]), "+r"(c[3])
        : "r"(a[0]), "r"(a[1]), "r"(a[2]), "r"(a[3]), "r"(b0), "r"(b1));
}

// A source: 64-row half h of a 128-row packed block; two 2KB pieces per k-block.
DEVFN void stage_copy(uint8_t* smem, int st, const uint8_t* gA128, int h,
                      const uint8_t* gG, const uint8_t* gU, int kb, int tid) {
    uint8_t* base = smem + st * STAGE_B;
    size_t kboff = (size_t)kb * 8192;
    #pragma unroll
    for (int c5 = 0; c5 < 5; c5++) {
        int c = c5 * 256 + tid;
        const uint8_t* src;
        if (c < 256) {
            int piece = c >> 7, off = (c & 127) << 4;
            src = gA128 + kboff + piece * 4096 + h * 2048 + off;
        } else if (c < 768) {
            src = gG + kboff + ((c - 256) << 4);
        } else {
            src = gU + kboff + ((c - 768) << 4);
        }
        uint32_t d0;
        asm("{ .reg .u64 t; cvta.to.shared.u64 t, %1; cvt.u32.u64 %0, t; }"
            : "=r"(d0) : "l"(base + (c << 4)));
        asm volatile("cp.async.cg.shared.global [%0], [%1], 16;" :: "r"(d0), "l"(src));
    }
}

#define PIPE_WAIT(kb) do { \
    if ((kb) < 30)       asm volatile("cp.async.wait_group 2;" ::: "memory"); \
    else if ((kb) == 30) asm volatile("cp.async.wait_group 1;" ::: "memory"); \
    else                 asm volatile("cp.async.wait_group 0;" ::: "memory"); \
} while (0)

__global__ void __launch_bounds__(256, 2) gemm_kernel() {
    extern __shared__ uint8_t smem[];
    int tid = threadIdx.x, lane = tid & 31, wid = tid >> 5;
    int mb = blockIdx.y, nb = blockIdx.x;

    const uint8_t* gA128 = d_qa + ((size_t)(mb >> 1) << 18);
    int h = mb & 1;
    const uint8_t* gG = d_qg + ((size_t)nb << 18);
    const uint8_t* gU = d_qu + ((size_t)nb << 18);

    #pragma unroll
    for (int st = 0; st < 3; st++) {
        stage_copy(smem, st, gA128, h, gG, gU, st, tid);
        asm volatile("cp.async.commit_group;" ::: "memory");
    }

    float wsg = d_wsinv[0], wsu = d_wsinv[1];
    int* sx = (int*)smem;
    int acc[64];
    #pragma unroll
    for (int k = 0; k < 64; k++) acc[k] = 0;

    if (wid < 4) {
        // ======= tensor warps (1/SMSP): m16 tile = wid, n [0,64), both mats =======
        for (int kb = 0; kb < KITERS; kb++) {
            PIPE_WAIT(kb);
            __syncthreads();
            if (kb + 3 < KITERS) {
                stage_copy(smem, (kb + 3) & 3, gA128, h, gG, gU, kb + 3, tid);
                asm volatile("cp.async.commit_group;" ::: "memory");
            }
            const uint8_t* sA = smem + (kb & 3) * STAGE_B;
            const uint8_t* sG = sA + A_B;
            const uint8_t* sU = sA + A_B + W_B;
            #pragma unroll
            for (int s = 0; s < 2; s++) {
                uint32_t af[4];
                {
                    uint4 v = *(const uint4*)(sA + (((s * 4 + wid) * 32 + lane) << 4));
                    af[0] = v.x; af[1] = v.y; af[2] = v.z; af[3] = v.w;
                }
                #pragma unroll
                for (int j8 = 0; j8 < 8; j8++) {
                    uint2 bg = *(const uint2*)(sG + (((s * 16 + j8) * 32 + lane) << 3));
                    uint2 bu = *(const uint2*)(sU + (((s * 16 + j8) * 32 + lane) << 3));
                    mma_s8(&acc[(j8 * 2 + 0) * 4], af, bg.x, bg.y);
                    mma_s8(&acc[(j8 * 2 + 1) * 4], af, bu.x, bu.y);
                }
            }
        }
        __syncthreads();   // A: compute done everywhere
        __syncthreads();   // B: sx published
        #pragma unroll
        for (int h2 = 0; h2 < 2; h2++) {
            int row = mb * 64 + wid * 16 + h2 * 8 + (lane >> 2);
            float ai = d_ainv[row];
            float sg = wsg * ai, su = wsu * ai;
            float* drow = d_h + (size_t)row * FDIM;
            #pragma unroll
            for (int j8 = 0; j8 < 8; j8++) {
                int n0 = nb * 128 + j8 * 8 + 2 * (lane & 3);
                float g0 = (float)acc[(j8 * 2 + 0) * 4 + h2 * 2] * sg;
                float g1 = (float)acc[(j8 * 2 + 0) * 4 + h2 * 2 + 1] * sg;
                float u0 = (float)acc[(j8 * 2 + 1) * 4 + h2 * 2] * su;
                float u1 = (float)acc[(j8 * 2 + 1) * 4 + h2 * 2 + 1] * su;
                float2 o;
                o.x = g0 / (1.f + __expf(-g0)) * u0;
                o.y = g1 / (1.f + __expf(-g1)) * u1;
                *(float2*)(drow + n0) = o;
            }
        }
    } else {
        // ======= dp4a warps (1/SMSP): n [64,128), one mat, 32 rows =======
        int dw = wid - 4;
        int mat = dw & 1, rblk = dw >> 1;
        int mrow = lane >> 3, ncol = lane & 7;
        int i4 = rblk * 2 + (mrow >> 1);
        int r0 = (mrow & 1) * 4;
        for (int kb = 0; kb < KITERS; kb++) {
            PIPE_WAIT(kb);
            __syncthreads();
            if (kb + 3 < KITERS) {
                stage_copy(smem, (kb + 3) & 3, gA128, h, gG, gU, kb + 3, tid);
                asm volatile("cp.async.commit_group;" ::: "memory");
            }
            const uint8_t* sA = smem + (kb & 3) * STAGE_B;
            const uint8_t* sB = sA + A_B + (mat ? W_B : 0);
            #pragma unroll
            for (int s = 0; s < 2; s++) {
                #pragma unroll
                for (int g2 = 0; g2 < 4; g2++) {
                    int b0 = (((s * 16 + 8) * 32 + ncol * 4 + g2) << 3);
                    int bv0[8], bv1[8];
                    #pragma unroll
                    for (int j = 0; j < 8; j++) {
                        int2 b2 = *(const int2*)(sB + b0 + (j << 8));
                        bv0[j] = b2.x; bv1[j] = b2.y;
                    }
                    int a0 = (((s * 4 + i4) * 32 + g2) << 4) + r0;
                    #pragma unroll
                    for (int i = 0; i < 8; i++) {
                        const uint8_t* p = sA + a0 + (i << 6);
                        int av0 = *(const int*)p;
                        int av1 = *(const int*)(p + 8);
                        #pragma unroll
                        for (int j = 0; j < 8; j++)
                            acc[i * 8 + j] = __dp4a(av1, bv1[j],
                                             __dp4a(av0, bv0[j], acc[i * 8 + j]));
                    }
                }
            }
        }
        __syncthreads();   // A
        if (mat == 0) {
            #pragma unroll
            for (int i = 0; i < 8; i++)
                #pragma unroll
                for (int j = 0; j < 8; j++)
                    sx[(rblk * 32 + mrow * 8 + i) * 64 + j * 8 + ncol] = acc[i * 8 + j];
        }
        __syncthreads();   // B
        if (mat == 1) {
            #pragma unroll
            for (int i = 0; i < 8; i++) {
                int row = mb * 64 + rblk * 32 + mrow * 8 + i;
                float ai = d_ainv[row];
                float sg = wsg * ai, su = wsu * ai;
                float* drow = d_h + (size_t)row * FDIM + nb * 128 + 64;
                #pragma unroll
                for (int j = 0; j < 8; j++) {
                    float g = (float)sx[(rblk * 32 + mrow * 8 + i) * 64 + j * 8 + ncol] * sg;
                    float u = (float)acc[i * 8 + j] * su;
                    drow[j * 8 + ncol] = g / (1.f + __expf(-g)) * u;
                }
            }
        }
    }
}

// ---------------- K4: finalize Wd scale ----------------
__global__ void fin2_kernel() {
    int tid = threadIdx.x;
    double s = 0.0;
    for (int i = tid; i < 512; i += 256) s += (double)d_part[2 * 512 + i];
    #pragma unroll
    for (int o = 16; o; o >>= 1) s += __shfl_xor_sync(~0u, s, o);
    __shared__ double ds[8];
    if ((tid & 31) == 0) ds[tid >> 5] = s;
    __syncthreads();
    if (tid == 0) {
        double S = 0.0;
        #pragma unroll
        for (int k = 0; k < 8; k++) S += ds[k];
        d_wsinv[2] = (float)fmax(S / (double)WELEM, 1e-5);
    }
}

// ---------------- K5: v[f] = sum_d ternary(Wd[d,f]) ----------------
__global__ void vsum_kernel(const float* __restrict__ Wd) {
    int f = blockIdx.x * 256 + threadIdx.x;
    int d0 = blockIdx.y * 128;
    float ws = 1.0f / d_wsinv[2];
    float s = 0.f;
    #pragma unroll 4
    for (int d = 0; d < 128; d++)
        s += fminf(fmaxf(rintf(Wd[(size_t)(d0 + d) * FDIM + f] * ws), -1.f), 1.f);
    atomicAdd(&d_v[f], s);
}

// ---------------- K6: rmsnorm + act quant + dot with v ----------------
__global__ void hnorm_kernel(const float* __restrict__ lnw) {
    __shared__ float row[FDIM];
    __shared__ float red[8];
    __shared__ float bval;
    int t = blockIdx.x, tid = threadIdx.x;
    const float* src = d_h + (size_t)t * FDIM;
    float ss = 0.f;
    for (int i = tid; i < FDIM; i += 256) { float v = src[i]; row[i] = v; ss += v * v; }
    ss = wsum(ss);
    if ((tid & 31) == 0) red[tid >> 5] = ss;
    __syncthreads();
    if (tid == 0) {
        float S = 0.f;
        #pragma unroll
        for (int k = 0; k < 8; k++) S += red[k];
        bval = rsqrtf(S / (float)FDIM + 1e-6f);
    }
    __syncthreads();
    float rn = bval, mx = 0.f;
    for (int i = tid; i < FDIM; i += 256) {
        float v = row[i] * rn * lnw[i];
        row[i] = v;
        mx = fmaxf(mx, fabsf(v));
    }
    mx = wmax(mx);
    if ((tid & 31) == 0) red[tid >> 5] = mx;
    __syncthreads();
    if (tid == 0) {
        float M = 0.f;
        #pragma unroll
        for (int k = 0; k < 8; k++) M = fmaxf(M, red[k]);
        bval = fmaxf(M, 1e-5f);
    }
    __syncthreads();
    float clipv = bval, scale = 127.f / clipv, dot = 0.f;
    for (int i = tid; i < FDIM; i += 256) {
        float q = fminf(fmaxf(rintf(row[i] * scale), -128.f), 127.f);
        dot += q * d_v[i];
    }
    dot = wsum(dot);
    if ((tid & 31) == 0) red[tid >> 5] = dot;
    __syncthreads();
    if (tid == 0) {
        float S = 0.f;
        #pragma unroll
        for (int k = 0; k < 8; k++) S += red[k];
        d_tok[t] = S * (clipv / 127.f) * d_wsinv[2];
    }
}

// ---------------- K7: pool ----------------
__global__ void pool_kernel() {
    int g = blockIdx.x, tid = threadIdx.x;
    float v = d_tok[g * 128 + tid];
    v = wsum(v);
    __shared__ float r[4];
    if ((tid & 31) == 0) r[tid >> 5] = v;
    __syncthreads();
    if (tid == 0) d_pool[g] = (r[0] + r[1] + r[2] + r[3]) * (1.0f / (128.f * 2048.f));
}

// ---------------- K8: classifier ----------------
__global__ void cls_kernel(const float* __restrict__ W, const float* __restrict__ b,
                           float* __restrict__ out) {
    int i = blockIdx.x * 256 + threadIdx.x;
    if (i < 8000) {
        int bb = i / 1000, n = i % 1000;
        float s = b[n];
        #pragma unroll
        for (int c = 0; c < 3; c++) s += d_pool[bb * 3 + c] * W[n * 3 + c];
        out[i] = s;
    }
}

extern "C" void kernel_launch(void* const* d_in, const int* in_sizes, int n_in,
                              void* d_out, int out_size) {
    const float* x    = (const float*)d_in[0];
    const float* Wg   = (const float*)d_in[1];
    const float* Wu   = (const float*)d_in[2];
    const float* Wd   = (const float*)d_in[3];
    const float* lnw  = (const float*)d_in[4];
    const float* clsW = (const float*)d_in[5];
    const float* clsb = (const float*)d_in[6];
    float* out = (float*)d_out;

    cudaFuncSetAttribute(gemm_kernel, cudaFuncAttributeMaxDynamicSharedMemorySize, SMEM_GEMM);

    wred_kernel<<<dim3(512, 3), 256>>>(Wg, Wu, Wd);
    qw2_kernel<<<dim3(4096, 2), 256>>>(Wg, Wu);
    act_kernel<<<TOK, 256>>>(x);
    gemm_kernel<<<dim3(FDIM / BN, TOK / BM), 256, SMEM_GEMM>>>();
    fin2_kernel<<<1, 256>>>();
    vsum_kernel<<<dim3(32, 16), 256>>>(Wd);
    hnorm_kernel<<<TOK, 256>>>(lnw);
    pool_kernel<<<24, 128>>>();
    cls_kernel<<<32, 256>>>(clsW, clsb, out);
}